// round 7
// baseline (speedup 1.0000x reference)
#include <cuda_runtime.h>
#include <cuda_bf16.h>
#include <cstdint>

#define NENT   100000
#define NEDGE  500000
#define NSEED  10000
#define DIM    128
#define NTILE  782                  // ceil(NENT/128)
#define NROWPAD (NTILE * 128)       // 100096
#define NBLK_SCAN 98                // ceil(NENT/1024)

// dense tiling: block = 128(M) x 128(N) x 128(K), 8 warps (2m x 4n), warp tile 64x32
#define BM 128
#define BN 128
#define LDAH 136                    // halfs per row (padded stride)
#define LDAW 68                     // words per row
#define PLANEW (BM * LDAW)          // 8704 words per plane
#define SMEM_D (4 * PLANEW * 4)     // 139264 bytes

// ---------------- device scratch (per graph) ----------------
__device__ int   g_cntbuf[2][NENT];
__device__ int   g_rowptr[2][NENT + 1];
__device__ int   g_cursor[2][NENT];
__device__ int   g_col[2][2 * NEDGE];
__device__ float g_rinv[2][NENT];
__device__ float g_hid[2][(size_t)NENT * DIM];
__device__ float g_agg[2][(size_t)NROWPAD * DIM];   // zero-padded tail rows
__device__ int   g_bsum[2][NBLK_SCAN];

// ---------------- helpers ----------------
__device__ __forceinline__ uint32_t pack_bf16hi(float x0, float x1) {
    uint32_t u;
    asm("cvt.rn.bf16x2.f32 %0, %1, %2;" : "=r"(u) : "f"(x1), "f"(x0));
    return u;
}
__device__ __forceinline__ void mma_bf16(float* c, const uint32_t* a, const uint32_t* b) {
    asm volatile(
        "mma.sync.aligned.m16n8k16.row.col.f32.bf16.bf16.f32 "
        "{%0,%1,%2,%3}, {%4,%5,%6,%7}, {%8,%9}, {%0,%1,%2,%3};"
        : "+f"(c[0]), "+f"(c[1]), "+f"(c[2]), "+f"(c[3])
        : "r"(a[0]), "r"(a[1]), "r"(a[2]), "r"(a[3]), "r"(b[0]), "r"(b[1]));
}

// ---------------- zero both graphs' count arrays ----------------
__global__ void k_zero() {
    int i = blockIdx.x * 1024 + threadIdx.x;
    if (i < NENT) { g_cntbuf[0][i] = 0; g_cntbuf[1][i] = 0; }
}

// ---------------- graph build ----------------
__global__ void k_count(const int* __restrict__ edges, int wg) {
    int i = blockIdx.x * blockDim.x + threadIdx.x;
    if (i < NEDGE) {
        int2 e = ((const int2*)edges)[i];
        atomicAdd(&g_cntbuf[wg][e.x], 1);
        atomicAdd(&g_cntbuf[wg][e.y], 1);
    }
}

// per-block exclusive scan + rinv + block sums
__global__ void k_scan1(int wg) {
    __shared__ int wsum[32];
    const int* cnt = g_cntbuf[wg];
    int tid = threadIdx.x, lane = tid & 31, w = tid >> 5;
    int i = blockIdx.x * 1024 + tid;
    int v = (i < NENT) ? cnt[i] : 0;
    int x = v;
    #pragma unroll
    for (int off = 1; off < 32; off <<= 1) {
        int t = __shfl_up_sync(0xffffffffu, x, off);
        if (lane >= off) x += t;
    }
    if (lane == 31) wsum[w] = x;
    __syncthreads();
    if (w == 0) {
        int y = wsum[lane];
        #pragma unroll
        for (int off = 1; off < 32; off <<= 1) {
            int t = __shfl_up_sync(0xffffffffu, y, off);
            if (lane >= off) y += t;
        }
        wsum[lane] = y;
    }
    __syncthreads();
    int excl = ((w > 0) ? wsum[w - 1] : 0) + x - v;
    if (i < NENT) {
        g_rowptr[wg][i] = excl;
        g_rinv[wg][i] = rsqrtf((float)(v + 1));
    }
    if (tid == 1023) g_bsum[wg][blockIdx.x] = wsum[31];
}

// add cross-block offset
__global__ void k_scanadd(int wg) {
    __shared__ int s_off;
    int tid = threadIdx.x;
    if (tid < 32) {
        int s = 0;
        #pragma unroll
        for (int c = tid; c < NBLK_SCAN; c += 32)
            if (c < (int)blockIdx.x) s += g_bsum[wg][c];
        #pragma unroll
        for (int o = 16; o; o >>= 1) s += __shfl_xor_sync(0xffffffffu, s, o);
        if (tid == 0) s_off = s;
    }
    __syncthreads();
    int i = blockIdx.x * 1024 + tid;
    if (i < NENT) {
        int r = g_rowptr[wg][i] + s_off;
        g_rowptr[wg][i] = r;
        g_cursor[wg][i] = r;
    }
    if (i == 0) g_rowptr[wg][NENT] = 2 * NEDGE;
}

__global__ void k_fill(const int* __restrict__ edges, int wg) {
    int i = blockIdx.x * blockDim.x + threadIdx.x;
    if (i < NEDGE) {
        int2 e = ((const int2*)edges)[i];
        int p = atomicAdd(&g_cursor[wg][e.y], 1); g_col[wg][p] = e.x;
        int q = atomicAdd(&g_cursor[wg][e.x], 1); g_col[wg][q] = e.y;
    }
}

// ---------------- aggregation ----------------
__global__ void k_aggc(const float* __restrict__ x, int wg) {
    int gw   = (blockIdx.x * blockDim.x + threadIdx.x) >> 5;
    int lane = threadIdx.x & 31;
    if (gw >= NENT) return;
    int v = gw;
    int beg = g_rowptr[wg][v], end = g_rowptr[wg][v + 1];
    const int* col = g_col[wg];
    const float* rinv = g_rinv[wg];
    float rv = rinv[v];
    const float4* x4 = (const float4*)x;
    float4 a = x4[(size_t)v * 32 + lane];
    float selfn = rv * rv;
    float4 acc;
    acc.x = a.x * selfn; acc.y = a.y * selfn; acc.z = a.z * selfn; acc.w = a.w * selfn;
    int e = beg;
    for (; e + 4 <= end; e += 4) {
        int u0 = col[e], u1 = col[e + 1], u2 = col[e + 2], u3 = col[e + 3];
        float n0 = rv * rinv[u0], n1 = rv * rinv[u1];
        float n2 = rv * rinv[u2], n3 = rv * rinv[u3];
        float4 a0 = x4[(size_t)u0 * 32 + lane];
        float4 a1 = x4[(size_t)u1 * 32 + lane];
        float4 a2 = x4[(size_t)u2 * 32 + lane];
        float4 a3 = x4[(size_t)u3 * 32 + lane];
        acc.x = fmaf(a0.x, n0, acc.x); acc.y = fmaf(a0.y, n0, acc.y);
        acc.z = fmaf(a0.z, n0, acc.z); acc.w = fmaf(a0.w, n0, acc.w);
        acc.x = fmaf(a1.x, n1, acc.x); acc.y = fmaf(a1.y, n1, acc.y);
        acc.z = fmaf(a1.z, n1, acc.z); acc.w = fmaf(a1.w, n1, acc.w);
        acc.x = fmaf(a2.x, n2, acc.x); acc.y = fmaf(a2.y, n2, acc.y);
        acc.z = fmaf(a2.z, n2, acc.z); acc.w = fmaf(a2.w, n2, acc.w);
        acc.x = fmaf(a3.x, n3, acc.x); acc.y = fmaf(a3.y, n3, acc.y);
        acc.z = fmaf(a3.z, n3, acc.z); acc.w = fmaf(a3.w, n3, acc.w);
    }
    for (; e < end; e++) {
        int u = col[e];
        float nm = rv * rinv[u];
        float4 xu = x4[(size_t)u * 32 + lane];
        acc.x = fmaf(xu.x, nm, acc.x);
        acc.y = fmaf(xu.y, nm, acc.y);
        acc.z = fmaf(xu.z, nm, acc.z);
        acc.w = fmaf(xu.w, nm, acc.w);
    }
    ((float4*)g_agg[wg])[(size_t)v * 32 + lane] = acc;
}

// ---------------- dense: out = relu(agg @ W + xin), split-bf16 m16n8k16 ----------------
__global__ void __launch_bounds__(256, 1) k_dense_mma(const float* __restrict__ xin,
                                                      const float* __restrict__ Wg,
                                                      int wg,
                                                      float* __restrict__ out) {
    extern __shared__ uint32_t smem[];
    uint32_t* sAhi = smem;
    uint32_t* sAlo = sAhi + PLANEW;
    uint32_t* sBhi = sAlo + PLANEW;
    uint32_t* sBlo = sBhi + PLANEW;

    int tid = threadIdx.x;
    int bm = blockIdx.x;

    // stage A (128x128 fp32 -> bf16 hi/lo planes)
    {
        const float4* src = (const float4*)(g_agg[wg] + (size_t)bm * BM * DIM);
        #pragma unroll
        for (int t = 0; t < 16; t++) {
            int idx4 = tid + t * 256;
            int row = idx4 >> 5, col4 = (idx4 & 31) << 2;
            float4 f = src[idx4];
            uint32_t h0 = pack_bf16hi(f.x, f.y);
            uint32_t h1 = pack_bf16hi(f.z, f.w);
            float l0 = f.x - __uint_as_float(h0 << 16);
            float l1 = f.y - __uint_as_float(h0 & 0xffff0000u);
            float l2 = f.z - __uint_as_float(h1 << 16);
            float l3 = f.w - __uint_as_float(h1 & 0xffff0000u);
            int w = row * LDAW + (col4 >> 1);
            sAhi[w] = h0; sAhi[w + 1] = h1;
            sAlo[w] = pack_bf16hi(l0, l1);
            sAlo[w + 1] = pack_bf16hi(l2, l3);
        }
    }
    // stage W transposed (global [k][n] -> smem [n][k] bf16 hi/lo planes)
    {
        __nv_bfloat16* bhi = (__nv_bfloat16*)sBhi;
        __nv_bfloat16* blo = (__nv_bfloat16*)sBlo;
        const float4* src = (const float4*)Wg;
        #pragma unroll
        for (int t = 0; t < 16; t++) {
            int idx4 = tid + t * 256;
            int krow = idx4 >> 5, n4 = (idx4 & 31) << 2;
            float4 f = src[idx4];
            float vals[4] = { f.x, f.y, f.z, f.w };
            #pragma unroll
            for (int j = 0; j < 4; j++) {
                float v = vals[j];
                __nv_bfloat16 h = __float2bfloat16_rn(v);
                float l = v - __bfloat162float(h);
                int ha = (n4 + j) * LDAH + krow;
                bhi[ha] = h;
                blo[ha] = __float2bfloat16_rn(l);
            }
        }
    }
    __syncthreads();

    int wid = tid >> 5, lane = tid & 31;
    int warp_m = wid & 1, warp_n = wid >> 1;          // 2m x 4n, warp tile 64x32
    int g = lane >> 2, tig = lane & 3;

    float acc[4][4][4];
    #pragma unroll
    for (int mi = 0; mi < 4; mi++)
        #pragma unroll
        for (int ni = 0; ni < 4; ni++)
            #pragma unroll
            for (int q = 0; q < 4; q++) acc[mi][ni][q] = 0.f;

    int abase = (warp_m * 64 + g) * LDAW + tig;
    int bbase = (warp_n * 32 + g) * LDAW + tig;

    #pragma unroll
    for (int kk = 0; kk < 8; kk++) {
        int k0w = kk * 8;
        uint32_t ahi[4][4], alo[4][4];
        #pragma unroll
        for (int mi = 0; mi < 4; mi++) {
            int a0 = abase + mi * 16 * LDAW + k0w;
            ahi[mi][0] = sAhi[a0];
            ahi[mi][1] = sAhi[a0 + 8 * LDAW];
            ahi[mi][2] = sAhi[a0 + 4];
            ahi[mi][3] = sAhi[a0 + 8 * LDAW + 4];
            alo[mi][0] = sAlo[a0];
            alo[mi][1] = sAlo[a0 + 8 * LDAW];
            alo[mi][2] = sAlo[a0 + 4];
            alo[mi][3] = sAlo[a0 + 8 * LDAW + 4];
        }
        #pragma unroll
        for (int ni = 0; ni < 4; ni++) {
            int b0 = bbase + ni * 8 * LDAW + k0w;
            uint32_t bhi[2], blo[2];
            bhi[0] = sBhi[b0]; bhi[1] = sBhi[b0 + 4];
            blo[0] = sBlo[b0]; blo[1] = sBlo[b0 + 4];
            #pragma unroll
            for (int mi = 0; mi < 4; mi++) {
                mma_bf16(acc[mi][ni], ahi[mi], bhi);
                mma_bf16(acc[mi][ni], ahi[mi], blo);
                mma_bf16(acc[mi][ni], alo[mi], bhi);
            }
        }
    }

    // epilogue: residual + relu
    #pragma unroll
    for (int mi = 0; mi < 4; mi++) {
        int r0 = bm * BM + warp_m * 64 + mi * 16 + g;
        int r1 = r0 + 8;
        #pragma unroll
        for (int ni = 0; ni < 4; ni++) {
            int c = warp_n * 32 + ni * 8 + tig * 2;
            if (r0 < NENT) {
                float2 xv = *(const float2*)(xin + (size_t)r0 * DIM + c);
                float2 o;
                o.x = fmaxf(acc[mi][ni][0] + xv.x, 0.f);
                o.y = fmaxf(acc[mi][ni][1] + xv.y, 0.f);
                *(float2*)(out + (size_t)r0 * DIM + c) = o;
            }
            if (r1 < NENT) {
                float2 xv = *(const float2*)(xin + (size_t)r1 * DIM + c);
                float2 o;
                o.x = fmaxf(acc[mi][ni][2] + xv.x, 0.f);
                o.y = fmaxf(acc[mi][ni][3] + xv.y, 0.f);
                *(float2*)(out + (size_t)r1 * DIM + c) = o;
            }
        }
    }
}

// ---------------- seed gather ----------------
__global__ void k_seed(const int* __restrict__ seeds, const float* __restrict__ ent,
                       float* __restrict__ out) {
    int gw   = (blockIdx.x * blockDim.x + threadIdx.x) >> 5;
    int lane = threadIdx.x & 31;
    if (gw >= NSEED) return;
    int s = seeds[gw];
    ((float4*)out)[(size_t)gw * 32 + lane] = ((const float4*)ent)[(size_t)s * 32 + lane];
}

// ---------------- launch ----------------
static void run_pipeline(cudaStream_t st, int wg,
                         const int* edges, const float* emb, const int* seeds,
                         float* hid, float* ent_out, float* seed_out,
                         const float* W1, const float* W2) {
    int tE = (NEDGE + 255) / 256;
    k_count  <<<tE, 256, 0, st>>>(edges, wg);
    k_scan1  <<<NBLK_SCAN, 1024, 0, st>>>(wg);
    k_scanadd<<<NBLK_SCAN, 1024, 0, st>>>(wg);
    k_fill   <<<tE, 256, 0, st>>>(edges, wg);

    k_aggc     <<<12500, 256, 0, st>>>(emb, wg);
    k_dense_mma<<<NTILE, 256, SMEM_D, st>>>(emb, W1, wg, hid);
    k_aggc     <<<12500, 256, 0, st>>>(hid, wg);
    k_dense_mma<<<NTILE, 256, SMEM_D, st>>>(hid, W2, wg, ent_out);

    k_seed<<<(NSEED * 32 + 255) / 256, 256, 0, st>>>(seeds, ent_out, seed_out);
}

extern "C" void kernel_launch(void* const* d_in, const int* in_sizes, int n_in,
                              void* d_out, int out_size) {
    const int*   sr_seeds = (const int*)d_in[0];
    const int*   tg_seeds = (const int*)d_in[1];
    const float* emb_sr   = (const float*)d_in[4];
    const float* emb_tg   = (const float*)d_in[5];
    const int*   edges_sr = (const int*)d_in[6];
    const int*   edges_tg = (const int*)d_in[7];
    const float* W1       = (const float*)d_in[8];
    const float* W2       = (const float*)d_in[9];

    float* out         = (float*)d_out;
    float* sr_seed_out = out;
    float* tg_seed_out = out + (size_t)NSEED * DIM;
    float* sr_ent_out  = out + (size_t)2 * NSEED * DIM;
    float* tg_ent_out  = out + (size_t)2 * NSEED * DIM + (size_t)NENT * DIM;

    cudaFuncSetAttribute(k_dense_mma, cudaFuncAttributeMaxDynamicSharedMemorySize, SMEM_D);

    float *hid0 = nullptr, *hid1 = nullptr;
    cudaGetSymbolAddress((void**)&hid0, g_hid);
    hid1 = hid0 + (size_t)NENT * DIM;

    cudaStream_t s1;
    cudaStreamCreateWithFlags(&s1, cudaStreamNonBlocking);
    cudaEvent_t ev0, ev1;
    cudaEventCreateWithFlags(&ev0, cudaEventDisableTiming);
    cudaEventCreateWithFlags(&ev1, cudaEventDisableTiming);

    k_zero<<<NBLK_SCAN, 1024>>>();
    cudaEventRecord(ev0, 0);
    cudaStreamWaitEvent(s1, ev0, 0);

    run_pipeline(0,  0, edges_sr, emb_sr, sr_seeds, hid0, sr_ent_out, sr_seed_out, W1, W2);
    run_pipeline(s1, 1, edges_tg, emb_tg, tg_seeds, hid1, tg_ent_out, tg_seed_out, W1, W2);

    cudaEventRecord(ev1, s1);
    cudaStreamWaitEvent(0, ev1, 0);

    cudaEventDestroy(ev0);
    cudaEventDestroy(ev1);
    cudaStreamDestroy(s1);
}

// round 8
// speedup vs baseline: 1.2901x; 1.2901x over previous
#include <cuda_runtime.h>
#include <cuda_bf16.h>
#include <cstdint>

#define NENT   100000
#define NEDGE  500000
#define NSEED  10000
#define DIM    128
#define NTILE  782                  // ceil(NENT/128)
#define NROWPAD (NTILE * 128)       // 100096
#define NBLK_SCAN 98                // ceil(NENT/1024)

// dense tiling: block = 128(M) x 128(N) x 128(K), 8 warps (2m x 4n), warp tile 64x32
#define BM 128
#define BN 128
#define LDAH 136                    // halfs per row (padded stride)
#define LDAW 68                     // words per row
#define PLANEW (BM * LDAW)          // 8704 words per plane
#define SMEM_D (4 * PLANEW * 4)     // 139264 bytes

// ---------------- device scratch ----------------
__device__ int   g_cntbuf[2][NENT];
__device__ int   g_rowptr[NENT + 1];
__device__ int   g_cursor[NENT];
__device__ int   g_col[2 * NEDGE];
__device__ float g_rinv[NENT];
__device__ float g_hid[(size_t)NENT * DIM];
__device__ float g_agg[(size_t)NROWPAD * DIM];      // zero-padded tail rows
__device__ int   g_bsum[NBLK_SCAN];

// ---------------- helpers ----------------
__device__ __forceinline__ uint32_t pack_bf16hi(float x0, float x1) {
    uint32_t u;
    asm("cvt.rn.bf16x2.f32 %0, %1, %2;" : "=r"(u) : "f"(x1), "f"(x0));
    return u;
}
__device__ __forceinline__ void mma_bf16(float* c, const uint32_t* a, const uint32_t* b) {
    asm volatile(
        "mma.sync.aligned.m16n8k16.row.col.f32.bf16.bf16.f32 "
        "{%0,%1,%2,%3}, {%4,%5,%6,%7}, {%8,%9}, {%0,%1,%2,%3};"
        : "+f"(c[0]), "+f"(c[1]), "+f"(c[2]), "+f"(c[3])
        : "r"(a[0]), "r"(a[1]), "r"(a[2]), "r"(a[3]), "r"(b[0]), "r"(b[1]));
}

// ---------------- zero both graphs' count arrays ----------------
__global__ void k_zero() {
    int i = blockIdx.x * 1024 + threadIdx.x;
    if (i < NENT) { g_cntbuf[0][i] = 0; g_cntbuf[1][i] = 0; }
}

// ---------------- graph build ----------------
__global__ void k_count(const int* __restrict__ edges, int wg) {
    int i = blockIdx.x * blockDim.x + threadIdx.x;
    if (i < NEDGE) {
        int2 e = ((const int2*)edges)[i];
        atomicAdd(&g_cntbuf[wg][e.x], 1);
        atomicAdd(&g_cntbuf[wg][e.y], 1);
    }
}

// per-block exclusive scan + rinv + block sums
__global__ void k_scan1(int wg) {
    __shared__ int wsum[32];
    const int* cnt = g_cntbuf[wg];
    int tid = threadIdx.x, lane = tid & 31, w = tid >> 5;
    int i = blockIdx.x * 1024 + tid;
    int v = (i < NENT) ? cnt[i] : 0;
    int x = v;
    #pragma unroll
    for (int off = 1; off < 32; off <<= 1) {
        int t = __shfl_up_sync(0xffffffffu, x, off);
        if (lane >= off) x += t;
    }
    if (lane == 31) wsum[w] = x;
    __syncthreads();
    if (w == 0) {
        int y = wsum[lane];
        #pragma unroll
        for (int off = 1; off < 32; off <<= 1) {
            int t = __shfl_up_sync(0xffffffffu, y, off);
            if (lane >= off) y += t;
        }
        wsum[lane] = y;
    }
    __syncthreads();
    int excl = ((w > 0) ? wsum[w - 1] : 0) + x - v;
    if (i < NENT) {
        g_rowptr[i] = excl;
        g_rinv[i] = rsqrtf((float)(v + 1));
    }
    if (tid == 1023) g_bsum[blockIdx.x] = wsum[31];
}

// add cross-block offset
__global__ void k_scanadd() {
    __shared__ int s_off;
    int tid = threadIdx.x;
    if (tid < 32) {
        int s = 0;
        #pragma unroll
        for (int c = tid; c < NBLK_SCAN; c += 32)
            if (c < (int)blockIdx.x) s += g_bsum[c];
        #pragma unroll
        for (int o = 16; o; o >>= 1) s += __shfl_xor_sync(0xffffffffu, s, o);
        if (tid == 0) s_off = s;
    }
    __syncthreads();
    int i = blockIdx.x * 1024 + tid;
    if (i < NENT) {
        int r = g_rowptr[i] + s_off;
        g_rowptr[i] = r;
        g_cursor[i] = r;
    }
    if (i == 0) g_rowptr[NENT] = 2 * NEDGE;
}

__global__ void k_fill(const int* __restrict__ edges) {
    int i = blockIdx.x * blockDim.x + threadIdx.x;
    if (i < NEDGE) {
        int2 e = ((const int2*)edges)[i];
        int p = atomicAdd(&g_cursor[e.y], 1); g_col[p] = e.x;
        int q = atomicAdd(&g_cursor[e.x], 1); g_col[q] = e.y;
    }
}

// ---------------- aggregation ----------------
__global__ void k_aggc(const float* __restrict__ x) {
    int gw   = (blockIdx.x * blockDim.x + threadIdx.x) >> 5;
    int lane = threadIdx.x & 31;
    if (gw >= NENT) return;
    int v = gw;
    int beg = g_rowptr[v], end = g_rowptr[v + 1];
    const int* col = g_col;
    const float* rinv = g_rinv;
    float rv = rinv[v];
    const float4* x4 = (const float4*)x;
    float4 a = x4[(size_t)v * 32 + lane];
    float selfn = rv * rv;
    float4 acc;
    acc.x = a.x * selfn; acc.y = a.y * selfn; acc.z = a.z * selfn; acc.w = a.w * selfn;
    int e = beg;
    for (; e + 4 <= end; e += 4) {
        int u0 = col[e], u1 = col[e + 1], u2 = col[e + 2], u3 = col[e + 3];
        float n0 = rv * rinv[u0], n1 = rv * rinv[u1];
        float n2 = rv * rinv[u2], n3 = rv * rinv[u3];
        float4 a0 = x4[(size_t)u0 * 32 + lane];
        float4 a1 = x4[(size_t)u1 * 32 + lane];
        float4 a2 = x4[(size_t)u2 * 32 + lane];
        float4 a3 = x4[(size_t)u3 * 32 + lane];
        acc.x = fmaf(a0.x, n0, acc.x); acc.y = fmaf(a0.y, n0, acc.y);
        acc.z = fmaf(a0.z, n0, acc.z); acc.w = fmaf(a0.w, n0, acc.w);
        acc.x = fmaf(a1.x, n1, acc.x); acc.y = fmaf(a1.y, n1, acc.y);
        acc.z = fmaf(a1.z, n1, acc.z); acc.w = fmaf(a1.w, n1, acc.w);
        acc.x = fmaf(a2.x, n2, acc.x); acc.y = fmaf(a2.y, n2, acc.y);
        acc.z = fmaf(a2.z, n2, acc.z); acc.w = fmaf(a2.w, n2, acc.w);
        acc.x = fmaf(a3.x, n3, acc.x); acc.y = fmaf(a3.y, n3, acc.y);
        acc.z = fmaf(a3.z, n3, acc.z); acc.w = fmaf(a3.w, n3, acc.w);
    }
    for (; e < end; e++) {
        int u = col[e];
        float nm = rv * rinv[u];
        float4 xu = x4[(size_t)u * 32 + lane];
        acc.x = fmaf(xu.x, nm, acc.x);
        acc.y = fmaf(xu.y, nm, acc.y);
        acc.z = fmaf(xu.z, nm, acc.z);
        acc.w = fmaf(xu.w, nm, acc.w);
    }
    ((float4*)g_agg)[(size_t)v * 32 + lane] = acc;
}

// ---------------- dense: out = relu(agg @ W + xin), split-bf16 m16n8k16 ----------------
__global__ void __launch_bounds__(256, 1) k_dense_mma(const float* __restrict__ xin,
                                                      const float* __restrict__ Wg,
                                                      float* __restrict__ out) {
    extern __shared__ uint32_t smem[];
    uint32_t* sAhi = smem;
    uint32_t* sAlo = sAhi + PLANEW;
    uint32_t* sBhi = sAlo + PLANEW;
    uint32_t* sBlo = sBhi + PLANEW;

    int tid = threadIdx.x;
    int bm = blockIdx.x;

    // stage A (128x128 fp32 -> bf16 hi/lo planes)
    {
        const float4* src = (const float4*)(g_agg + (size_t)bm * BM * DIM);
        #pragma unroll
        for (int t = 0; t < 16; t++) {
            int idx4 = tid + t * 256;
            int row = idx4 >> 5, col4 = (idx4 & 31) << 2;
            float4 f = src[idx4];
            uint32_t h0 = pack_bf16hi(f.x, f.y);
            uint32_t h1 = pack_bf16hi(f.z, f.w);
            float l0 = f.x - __uint_as_float(h0 << 16);
            float l1 = f.y - __uint_as_float(h0 & 0xffff0000u);
            float l2 = f.z - __uint_as_float(h1 << 16);
            float l3 = f.w - __uint_as_float(h1 & 0xffff0000u);
            int w = row * LDAW + (col4 >> 1);
            sAhi[w] = h0; sAhi[w + 1] = h1;
            sAlo[w] = pack_bf16hi(l0, l1);
            sAlo[w + 1] = pack_bf16hi(l2, l3);
        }
    }
    // stage W transposed (global [k][n] -> smem [n][k] bf16 hi/lo planes)
    {
        __nv_bfloat16* bhi = (__nv_bfloat16*)sBhi;
        __nv_bfloat16* blo = (__nv_bfloat16*)sBlo;
        const float4* src = (const float4*)Wg;
        #pragma unroll
        for (int t = 0; t < 16; t++) {
            int idx4 = tid + t * 256;
            int krow = idx4 >> 5, n4 = (idx4 & 31) << 2;
            float4 f = src[idx4];
            float vals[4] = { f.x, f.y, f.z, f.w };
            #pragma unroll
            for (int j = 0; j < 4; j++) {
                float v = vals[j];
                __nv_bfloat16 h = __float2bfloat16_rn(v);
                float l = v - __bfloat162float(h);
                int ha = (n4 + j) * LDAH + krow;
                bhi[ha] = h;
                blo[ha] = __float2bfloat16_rn(l);
            }
        }
    }
    __syncthreads();

    int wid = tid >> 5, lane = tid & 31;
    int warp_m = wid & 1, warp_n = wid >> 1;          // 2m x 4n, warp tile 64x32
    int g = lane >> 2, tig = lane & 3;

    float acc[4][4][4];
    #pragma unroll
    for (int mi = 0; mi < 4; mi++)
        #pragma unroll
        for (int ni = 0; ni < 4; ni++)
            #pragma unroll
            for (int q = 0; q < 4; q++) acc[mi][ni][q] = 0.f;

    int abase = (warp_m * 64 + g) * LDAW + tig;
    int bbase = (warp_n * 32 + g) * LDAW + tig;

    #pragma unroll
    for (int kk = 0; kk < 8; kk++) {
        int k0w = kk * 8;
        uint32_t ahi[4][4], alo[4][4];
        #pragma unroll
        for (int mi = 0; mi < 4; mi++) {
            int a0 = abase + mi * 16 * LDAW + k0w;
            ahi[mi][0] = sAhi[a0];
            ahi[mi][1] = sAhi[a0 + 8 * LDAW];
            ahi[mi][2] = sAhi[a0 + 4];
            ahi[mi][3] = sAhi[a0 + 8 * LDAW + 4];
            alo[mi][0] = sAlo[a0];
            alo[mi][1] = sAlo[a0 + 8 * LDAW];
            alo[mi][2] = sAlo[a0 + 4];
            alo[mi][3] = sAlo[a0 + 8 * LDAW + 4];
        }
        #pragma unroll
        for (int ni = 0; ni < 4; ni++) {
            int b0 = bbase + ni * 8 * LDAW + k0w;
            uint32_t bhi[2], blo[2];
            bhi[0] = sBhi[b0]; bhi[1] = sBhi[b0 + 4];
            blo[0] = sBlo[b0]; blo[1] = sBlo[b0 + 4];
            #pragma unroll
            for (int mi = 0; mi < 4; mi++) {
                mma_bf16(acc[mi][ni], ahi[mi], bhi);
                mma_bf16(acc[mi][ni], ahi[mi], blo);
                mma_bf16(acc[mi][ni], alo[mi], bhi);
            }
        }
    }

    // epilogue: residual + relu
    #pragma unroll
    for (int mi = 0; mi < 4; mi++) {
        int r0 = bm * BM + warp_m * 64 + mi * 16 + g;
        int r1 = r0 + 8;
        #pragma unroll
        for (int ni = 0; ni < 4; ni++) {
            int c = warp_n * 32 + ni * 8 + tig * 2;
            if (r0 < NENT) {
                float2 xv = *(const float2*)(xin + (size_t)r0 * DIM + c);
                float2 o;
                o.x = fmaxf(acc[mi][ni][0] + xv.x, 0.f);
                o.y = fmaxf(acc[mi][ni][1] + xv.y, 0.f);
                *(float2*)(out + (size_t)r0 * DIM + c) = o;
            }
            if (r1 < NENT) {
                float2 xv = *(const float2*)(xin + (size_t)r1 * DIM + c);
                float2 o;
                o.x = fmaxf(acc[mi][ni][2] + xv.x, 0.f);
                o.y = fmaxf(acc[mi][ni][3] + xv.y, 0.f);
                *(float2*)(out + (size_t)r1 * DIM + c) = o;
            }
        }
    }
}

// ---------------- seed gather ----------------
__global__ void k_seed(const int* __restrict__ seeds, const float* __restrict__ ent,
                       float* __restrict__ out) {
    int gw   = (blockIdx.x * blockDim.x + threadIdx.x) >> 5;
    int lane = threadIdx.x & 31;
    if (gw >= NSEED) return;
    int s = seeds[gw];
    ((float4*)out)[(size_t)gw * 32 + lane] = ((const float4*)ent)[(size_t)s * 32 + lane];
}

// ---------------- launch (strictly serial, single stream) ----------------
extern "C" void kernel_launch(void* const* d_in, const int* in_sizes, int n_in,
                              void* d_out, int out_size) {
    const int*   sr_seeds = (const int*)d_in[0];
    const int*   tg_seeds = (const int*)d_in[1];
    const float* emb_sr   = (const float*)d_in[4];
    const float* emb_tg   = (const float*)d_in[5];
    const int*   edges_sr = (const int*)d_in[6];
    const int*   edges_tg = (const int*)d_in[7];
    const float* W1       = (const float*)d_in[8];
    const float* W2       = (const float*)d_in[9];

    float* out         = (float*)d_out;
    float* sr_seed_out = out;
    float* tg_seed_out = out + (size_t)NSEED * DIM;
    float* sr_ent_out  = out + (size_t)2 * NSEED * DIM;
    float* tg_ent_out  = out + (size_t)2 * NSEED * DIM + (size_t)NENT * DIM;

    cudaFuncSetAttribute(k_dense_mma, cudaFuncAttributeMaxDynamicSharedMemorySize, SMEM_D);

    float* hid = nullptr;
    cudaGetSymbolAddress((void**)&hid, g_hid);

    int tE = (NEDGE + 255) / 256;

    k_zero<<<NBLK_SCAN, 1024>>>();

    for (int g = 0; g < 2; g++) {
        const int*   edges = g ? edges_tg : edges_sr;
        const float* emb   = g ? emb_tg : emb_sr;
        const int*   seeds = g ? tg_seeds : sr_seeds;
        float* ent_out  = g ? tg_ent_out : sr_ent_out;
        float* seed_out = g ? tg_seed_out : sr_seed_out;

        k_count  <<<tE, 256>>>(edges, g);
        k_scan1  <<<NBLK_SCAN, 1024>>>(g);
        k_scanadd<<<NBLK_SCAN, 1024>>>();
        k_fill   <<<tE, 256>>>(edges);

        k_aggc     <<<12500, 256>>>(emb);
        k_dense_mma<<<NTILE, 256, SMEM_D>>>(emb, W1, hid);
        k_aggc     <<<12500, 256>>>(hid);
        k_dense_mma<<<NTILE, 256, SMEM_D>>>(hid, W2, ent_out);

        k_seed<<<(NSEED * 32 + 255) / 256, 256>>>(seeds, ent_out, seed_out);
    }
}